// round 1
// baseline (speedup 1.0000x reference)
#include <cuda_runtime.h>

typedef unsigned long long ull;

#define HID   128
#define TT    512
#define NB    2048
#define RPC   16            // batch rows per CTA
#define NCTA  (NB / RPC)    // 128
#define NTHR  256

// Blocked-transposed weights: [k/4][gate*128+j][k%4] (float4-coalesced per (gate,j))
// 0: Wh0, 1: Wi1, 2: Wh1
__device__ __align__(16) float g_wt[3][128 * 384];

__global__ void transpose_k(const float* __restrict__ Wh0,
                            const float* __restrict__ Wi1,
                            const float* __restrict__ Wh1) {
    int idx = blockIdx.x * blockDim.x + threadIdx.x;
    if (idx >= 128 * 384) return;
    int kq  = idx / 1536;
    int rem = idx - kq * 1536;
    int gj  = rem >> 2;
    int k   = kq * 4 + (rem & 3);
    g_wt[0][idx] = Wh0[gj * HID + k];
    g_wt[1][idx] = Wi1[gj * HID + k];
    g_wt[2][idx] = Wh1[gj * HID + k];
}

// ---- packed f32x2 helpers (sm_100+) ----
__device__ __forceinline__ ull splat2(float w) {
    ull r; asm("mov.b64 %0, {%1, %1};" : "=l"(r) : "f"(w)); return r;
}
__device__ __forceinline__ void ffma2(ull& d, ull a, ull b) {
    asm("fma.rn.f32x2 %0, %1, %2, %0;" : "+l"(d) : "l"(a), "l"(b));
}
__device__ __forceinline__ void unpack2(ull v, float& lo, float& hi) {
    asm("mov.b64 {%0, %1}, %2;" : "=f"(lo), "=f"(hi) : "l"(v));
}
__device__ __forceinline__ float f4c(const float4& v, int i) {
    switch (i & 3) { case 0: return v.x; case 1: return v.y; case 2: return v.z; default: return v.w; }
}
__device__ __forceinline__ float pick8(const float4& a, const float4& b, int i) {
    return (i < 4) ? f4c(a, i) : f4c(b, i - 4);
}
__device__ __forceinline__ float sigf(float y) {
    return __fdividef(1.f, 1.f + __expf(-y));
}
__device__ __forceinline__ float tanhf_fast(float x) {
    return 2.f * sigf(2.f * x) - 1.f;
}

__global__ void __launch_bounds__(NTHR, 1)
gru_kernel(const float* __restrict__ x,
           const float* __restrict__ noise_z,
           const float* __restrict__ context,
           const float* __restrict__ Wi0,
           const float* __restrict__ bi0,
           const float* __restrict__ bh0,
           const float* __restrict__ bi1,
           const float* __restrict__ bh1,
           const float* __restrict__ Wa,
           const float* __restrict__ ba,
           float* __restrict__ out) {
    __shared__ __align__(16) float h0s[128 * 16];   // [k][r]
    __shared__ __align__(16) float h1s[128 * 16];   // [k][r]
    __shared__ __align__(16) float ctxgi[384 * 16]; // [gj][r]  (bi0 + context @ Wi0[:,2:12])
    __shared__ __align__(16) float decs[2 * 16];    // [s][r]   feedback input
    __shared__ __align__(16) float was[2 * 128];    // Wa staged

    const int tid = threadIdx.x;
    const int hf  = tid >> 7;       // half: 0/1
    const int j   = tid & 127;      // output neuron
    const int r0  = hf * 8;         // first of 8 rows this thread owns
    const int brow0 = blockIdx.x * RPC;

    // init shared
    for (int i = tid; i < 128 * 16; i += NTHR) { h0s[i] = 0.f; h1s[i] = 0.f; }
    was[tid] = Wa[tid]; // 256 == 2*128
    if (tid < 32) {
        int r = tid >> 1, s = tid & 1;
        decs[s * 16 + r] = noise_z[(brow0 + r) * 2 + s];
    }

    // persistent per-thread constants
    float wi00[3], wi01[3];
    ull bh0p[3], bi1p[3], bh1p[3];
#pragma unroll
    for (int g = 0; g < 3; ++g) {
        int gj = g * 128 + j;
        wi00[g] = Wi0[gj * 12 + 0];
        wi01[g] = Wi0[gj * 12 + 1];
        bh0p[g] = splat2(bh0[gj]);
        bi1p[g] = splat2(bi1[gj]);
        bh1p[g] = splat2(bh1[gj]);
    }

    // ctxgi: bi0 + context-part of layer-0 input gates (time-invariant)
#pragma unroll
    for (int g = 0; g < 3; ++g) {
        int gj = g * 128 + j;
        float wrow[10];
#pragma unroll
        for (int e = 0; e < 10; ++e) wrow[e] = Wi0[gj * 12 + 2 + e];
        float b = bi0[gj];
        for (int rr = 0; rr < 8; ++rr) {
            int r = r0 + rr;
            float acc = b;
#pragma unroll
            for (int e = 0; e < 10; ++e) acc += context[(brow0 + r) * 10 + e] * wrow[e];
            ctxgi[gj * 16 + r] = acc;
        }
    }
    __syncthreads();

    const float4* w0p = reinterpret_cast<const float4*>(g_wt[0]) + j;
    const float4* wip = reinterpret_cast<const float4*>(g_wt[1]) + j;
    const float4* whp = reinterpret_cast<const float4*>(g_wt[2]) + j;

    for (int t = -1; t < TT; ++t) {
        // ================= layer 0: gh0 = h0 @ Wh0^T + bh0 =================
        ull a0[3][4];
#pragma unroll
        for (int g = 0; g < 3; ++g)
#pragma unroll
            for (int p = 0; p < 4; ++p) a0[g][p] = bh0p[g];

#pragma unroll 2
        for (int kq = 0; kq < 32; ++kq) {
            float4 w0 = w0p[kq * 384];
            float4 w1 = w0p[kq * 384 + 128];
            float4 w2 = w0p[kq * 384 + 256];
            const float* hb = &h0s[kq * 64 + r0];
#pragma unroll
            for (int kr = 0; kr < 4; ++kr) {
                ulonglong2 hA = *reinterpret_cast<const ulonglong2*>(hb + kr * 16);
                ulonglong2 hB = *reinterpret_cast<const ulonglong2*>(hb + kr * 16 + 4);
                ull s0 = splat2(f4c(w0, kr));
                ull s1 = splat2(f4c(w1, kr));
                ull s2 = splat2(f4c(w2, kr));
                ffma2(a0[0][0], s0, hA.x); ffma2(a0[0][1], s0, hA.y);
                ffma2(a0[0][2], s0, hB.x); ffma2(a0[0][3], s0, hB.y);
                ffma2(a0[1][0], s1, hA.x); ffma2(a0[1][1], s1, hA.y);
                ffma2(a0[1][2], s1, hB.x); ffma2(a0[1][3], s1, hB.y);
                ffma2(a0[2][0], s2, hA.x); ffma2(a0[2][1], s2, hA.y);
                ffma2(a0[2][2], s2, hB.x); ffma2(a0[2][3], s2, hB.y);
            }
        }

        // layer-0 epilogue
        {
            float ghv[3][8];
#pragma unroll
            for (int g = 0; g < 3; ++g)
#pragma unroll
                for (int p = 0; p < 4; ++p) unpack2(a0[g][p], ghv[g][2 * p], ghv[g][2 * p + 1]);

            float4 cg0a = *reinterpret_cast<const float4*>(&ctxgi[(0 * 128 + j) * 16 + r0]);
            float4 cg0b = *reinterpret_cast<const float4*>(&ctxgi[(0 * 128 + j) * 16 + r0 + 4]);
            float4 cg1a = *reinterpret_cast<const float4*>(&ctxgi[(1 * 128 + j) * 16 + r0]);
            float4 cg1b = *reinterpret_cast<const float4*>(&ctxgi[(1 * 128 + j) * 16 + r0 + 4]);
            float4 cg2a = *reinterpret_cast<const float4*>(&ctxgi[(2 * 128 + j) * 16 + r0]);
            float4 cg2b = *reinterpret_cast<const float4*>(&ctxgi[(2 * 128 + j) * 16 + r0 + 4]);
            float4 d0a = *reinterpret_cast<const float4*>(&decs[r0]);
            float4 d0b = *reinterpret_cast<const float4*>(&decs[r0 + 4]);
            float4 d1a = *reinterpret_cast<const float4*>(&decs[16 + r0]);
            float4 d1b = *reinterpret_cast<const float4*>(&decs[16 + r0 + 4]);
            float4 hoa = *reinterpret_cast<const float4*>(&h0s[j * 16 + r0]);
            float4 hob = *reinterpret_cast<const float4*>(&h0s[j * 16 + r0 + 4]);

            float h0n[8];
#pragma unroll
            for (int rr = 0; rr < 8; ++rr) {
                float d0 = pick8(d0a, d0b, rr), d1 = pick8(d1a, d1b, rr);
                float gir = pick8(cg0a, cg0b, rr) + d0 * wi00[0] + d1 * wi01[0] + ghv[0][rr];
                float giz = pick8(cg1a, cg1b, rr) + d0 * wi00[1] + d1 * wi01[1] + ghv[1][rr];
                float rg = sigf(gir);
                float zg = sigf(giz);
                float gn = pick8(cg2a, cg2b, rr) + d0 * wi00[2] + d1 * wi01[2] + rg * ghv[2][rr];
                float ng = tanhf_fast(gn);
                float ho = pick8(hoa, hob, rr);
                h0n[rr] = ng + zg * (ho - ng);
            }
            __syncthreads();  // everyone done reading old h0s
            *reinterpret_cast<float4*>(&h0s[j * 16 + r0])     = make_float4(h0n[0], h0n[1], h0n[2], h0n[3]);
            *reinterpret_cast<float4*>(&h0s[j * 16 + r0 + 4]) = make_float4(h0n[4], h0n[5], h0n[6], h0n[7]);
            __syncthreads();  // new h0 visible
        }

        // ====== layer 1: gi1 = h0n @ Wi1^T + bi1 ; gh1 = h1 @ Wh1^T + bh1 ======
        ull ai[3][4], ah[3][4];
#pragma unroll
        for (int g = 0; g < 3; ++g)
#pragma unroll
            for (int p = 0; p < 4; ++p) { ai[g][p] = bi1p[g]; ah[g][p] = bh1p[g]; }

        for (int kq = 0; kq < 32; ++kq) {
            float4 u0 = wip[kq * 384];
            float4 u1 = wip[kq * 384 + 128];
            float4 u2 = wip[kq * 384 + 256];
            float4 v0 = whp[kq * 384];
            float4 v1 = whp[kq * 384 + 128];
            float4 v2 = whp[kq * 384 + 256];
            const float* hb0 = &h0s[kq * 64 + r0];
            const float* hb1 = &h1s[kq * 64 + r0];
#pragma unroll
            for (int kr = 0; kr < 4; ++kr) {
                ulonglong2 aA = *reinterpret_cast<const ulonglong2*>(hb0 + kr * 16);
                ulonglong2 aB = *reinterpret_cast<const ulonglong2*>(hb0 + kr * 16 + 4);
                ulonglong2 bA = *reinterpret_cast<const ulonglong2*>(hb1 + kr * 16);
                ulonglong2 bB = *reinterpret_cast<const ulonglong2*>(hb1 + kr * 16 + 4);
                ull su0 = splat2(f4c(u0, kr));
                ull su1 = splat2(f4c(u1, kr));
                ull su2 = splat2(f4c(u2, kr));
                ull sv0 = splat2(f4c(v0, kr));
                ull sv1 = splat2(f4c(v1, kr));
                ull sv2 = splat2(f4c(v2, kr));
                ffma2(ai[0][0], su0, aA.x); ffma2(ai[0][1], su0, aA.y);
                ffma2(ai[0][2], su0, aB.x); ffma2(ai[0][3], su0, aB.y);
                ffma2(ai[1][0], su1, aA.x); ffma2(ai[1][1], su1, aA.y);
                ffma2(ai[1][2], su1, aB.x); ffma2(ai[1][3], su1, aB.y);
                ffma2(ai[2][0], su2, aA.x); ffma2(ai[2][1], su2, aA.y);
                ffma2(ai[2][2], su2, aB.x); ffma2(ai[2][3], su2, aB.y);
                ffma2(ah[0][0], sv0, bA.x); ffma2(ah[0][1], sv0, bA.y);
                ffma2(ah[0][2], sv0, bB.x); ffma2(ah[0][3], sv0, bB.y);
                ffma2(ah[1][0], sv1, bA.x); ffma2(ah[1][1], sv1, bA.y);
                ffma2(ah[1][2], sv1, bB.x); ffma2(ah[1][3], sv1, bB.y);
                ffma2(ah[2][0], sv2, bA.x); ffma2(ah[2][1], sv2, bA.y);
                ffma2(ah[2][2], sv2, bB.x); ffma2(ah[2][3], sv2, bB.y);
            }
        }

        // layer-1 epilogue
        {
            float giv[3][8], ghv[3][8];
#pragma unroll
            for (int g = 0; g < 3; ++g)
#pragma unroll
                for (int p = 0; p < 4; ++p) {
                    unpack2(ai[g][p], giv[g][2 * p], giv[g][2 * p + 1]);
                    unpack2(ah[g][p], ghv[g][2 * p], ghv[g][2 * p + 1]);
                }
            float4 hoa = *reinterpret_cast<const float4*>(&h1s[j * 16 + r0]);
            float4 hob = *reinterpret_cast<const float4*>(&h1s[j * 16 + r0 + 4]);
            float h1n[8];
#pragma unroll
            for (int rr = 0; rr < 8; ++rr) {
                float rg = sigf(giv[0][rr] + ghv[0][rr]);
                float zg = sigf(giv[1][rr] + ghv[1][rr]);
                float ng = tanhf_fast(giv[2][rr] + rg * ghv[2][rr]);
                float ho = pick8(hoa, hob, rr);
                h1n[rr] = ng + zg * (ho - ng);
            }
            __syncthreads();  // everyone done reading old h1s
            *reinterpret_cast<float4*>(&h1s[j * 16 + r0])     = make_float4(h1n[0], h1n[1], h1n[2], h1n[3]);
            *reinterpret_cast<float4*>(&h1s[j * 16 + r0 + 4]) = make_float4(h1n[4], h1n[5], h1n[6], h1n[7]);
            __syncthreads();  // new h1 visible
        }

        // ========== output head + autoregressive feedback ==========
        if (tid < 32) {
            int r = tid >> 1, s = tid & 1;
            if (t >= 0) {
                float acc0 = 0.f, acc1 = 0.f, acc2 = 0.f, acc3 = 0.f;
#pragma unroll 8
                for (int jj = 0; jj < 128; jj += 4) {
                    acc0 += h1s[(jj + 0) * 16 + r] * was[s * 128 + jj + 0];
                    acc1 += h1s[(jj + 1) * 16 + r] * was[s * 128 + jj + 1];
                    acc2 += h1s[(jj + 2) * 16 + r] * was[s * 128 + jj + 2];
                    acc3 += h1s[(jj + 3) * 16 + r] * was[s * 128 + jj + 3];
                }
                float o = ba[s] + ((acc0 + acc1) + (acc2 + acc3));
                decs[s * 16 + r] = o;
                out[(size_t)(brow0 + r) * (TT * 2) + t * 2 + s] = o;
            } else {
                // first scan input is x[:, 0], not the begin_state output
                decs[s * 16 + r] = x[(size_t)(brow0 + r) * (TT * 2) + s];
            }
        }
        __syncthreads();  // decs visible for next step's layer-0 epilogue
    }
}

extern "C" void kernel_launch(void* const* d_in, const int* in_sizes, int n_in,
                              void* d_out, int out_size) {
    const float* x       = (const float*)d_in[0];
    const float* noise_z = (const float*)d_in[1];
    const float* context = (const float*)d_in[2];
    const float* Wi0     = (const float*)d_in[3];
    const float* Wh0     = (const float*)d_in[4];
    const float* bi0     = (const float*)d_in[5];
    const float* bh0     = (const float*)d_in[6];
    const float* Wi1     = (const float*)d_in[7];
    const float* Wh1     = (const float*)d_in[8];
    const float* bi1     = (const float*)d_in[9];
    const float* bh1     = (const float*)d_in[10];
    const float* Wa      = (const float*)d_in[11];
    const float* ba      = (const float*)d_in[12];
    float* out = (float*)d_out;

    transpose_k<<<192, 256>>>(Wh0, Wi1, Wh1);
    gru_kernel<<<NCTA, NTHR>>>(x, noise_z, context, Wi0, bi0, bh0, bi1, bh1, Wa, ba, out);
}

// round 2
// speedup vs baseline: 1.1201x; 1.1201x over previous
#include <cuda_runtime.h>

typedef unsigned long long ull;

#define HID   128
#define TT    512
#define NB    2048
#define RPC   16
#define NCTA  (NB / RPC)
#define NTHR  256

// Blocked weights: [kq][gate*128+j][k%4]  -> LDG.128 at (kq,g,j) yields W[g,j][4 consecutive k]
// 0: Wh0, 1: Wi1, 2: Wh1
__device__ __align__(16) float g_wt[3][128 * 384];

__global__ void transpose_k(const float* __restrict__ Wh0,
                            const float* __restrict__ Wi1,
                            const float* __restrict__ Wh1) {
    int idx = blockIdx.x * blockDim.x + threadIdx.x;
    if (idx >= 128 * 384) return;
    int kq  = idx / 1536;
    int rem = idx - kq * 1536;
    int gj  = rem >> 2;
    int k   = kq * 4 + (rem & 3);
    g_wt[0][idx] = Wh0[gj * HID + k];
    g_wt[1][idx] = Wi1[gj * HID + k];
    g_wt[2][idx] = Wh1[gj * HID + k];
}

// ---- packed f32x2 helpers ----
__device__ __forceinline__ ull pk2(float lo, float hi) {
    ull r; asm("mov.b64 %0, {%1, %2};" : "=l"(r) : "f"(lo), "f"(hi)); return r;
}
__device__ __forceinline__ void ffma2(ull& d, ull a, ull b) {
    asm("fma.rn.f32x2 %0, %1, %2, %0;" : "+l"(d) : "l"(a), "l"(b));
}
__device__ __forceinline__ float hadd2(ull v) {
    float lo, hi; asm("mov.b64 {%0, %1}, %2;" : "=f"(lo), "=f"(hi) : "l"(v)); return lo + hi;
}
__device__ __forceinline__ float f4c(const float4& v, int i) {
    switch (i & 3) { case 0: return v.x; case 1: return v.y; case 2: return v.z; default: return v.w; }
}
__device__ __forceinline__ float pick8(const float4& a, const float4& b, int i) {
    return (i < 4) ? f4c(a, i) : f4c(b, i - 4);
}
__device__ __forceinline__ float tanhap(float x) {
    float y; asm("tanh.approx.f32 %0, %1;" : "=f"(y) : "f"(x)); return y;
}
__device__ __forceinline__ float sigap(float x) {
    return fmaf(tanhap(0.5f * x), 0.5f, 0.5f);
}

__global__ void __launch_bounds__(NTHR, 1)
gru_kernel(const float* __restrict__ x,
           const float* __restrict__ noise_z,
           const float* __restrict__ context,
           const float* __restrict__ Wi0,
           const float* __restrict__ bi0,
           const float* __restrict__ bh0,
           const float* __restrict__ bi1,
           const float* __restrict__ bh1,
           const float* __restrict__ Wa,
           const float* __restrict__ ba,
           float* __restrict__ out) {
    // h stored [r][k]: LDS.128 over consecutive k = broadcast across j-lanes
    __shared__ __align__(16) float h0s[2][16][128];
    __shared__ __align__(16) float h1s[2][16][128];
    __shared__ __align__(16) float decs[2][16];

    const int tid = threadIdx.x;
    const int hf  = tid >> 7;
    const int j   = tid & 127;
    const int r0  = hf * 8;
    const int brow0 = blockIdx.x * RPC;

    for (int i = tid; i < 2 * 16 * 128; i += NTHR) {
        (&h0s[0][0][0])[i] = 0.f;
        (&h1s[0][0][0])[i] = 0.f;
    }
    if (tid < 32) {
        int r = tid >> 1, s = tid & 1;
        decs[s][r] = noise_z[(brow0 + r) * 2 + s];
    }

    // persistent per-thread constants
    float wd0[3], wd1[3];
    ull b0p[3];
#pragma unroll
    for (int g = 0; g < 3; ++g) {
        int gj = g * 128 + j;
        wd0[g] = Wi0[gj * 12 + 0];
        wd1[g] = Wi0[gj * 12 + 1];
        b0p[g] = pk2(bh0[gj], 0.f);
    }
    ull brzp[2], binp, bhnp;
    brzp[0] = pk2(bi1[0 * 128 + j] + bh1[0 * 128 + j], 0.f);
    brzp[1] = pk2(bi1[1 * 128 + j] + bh1[1 * 128 + j], 0.f);
    binp = pk2(bi1[2 * 128 + j], 0.f);
    bhnp = pk2(bh1[2 * 128 + j], 0.f);

    // ctx gates: bi0 + context-part (time invariant), kept in registers
    float cg[3][8];
#pragma unroll
    for (int g = 0; g < 3; ++g) {
        int gj = g * 128 + j;
        float wrow[10];
#pragma unroll
        for (int e = 0; e < 10; ++e) wrow[e] = Wi0[gj * 12 + 2 + e];
        float b = bi0[gj];
        for (int rr = 0; rr < 8; ++rr) {
            float acc = b;
#pragma unroll
            for (int e = 0; e < 10; ++e) acc += context[(brow0 + r0 + rr) * 10 + e] * wrow[e];
            cg[g][rr] = acc;
        }
    }

    // head role: thread -> (row hr, state hs, k-slice hl)
    const int hr = tid >> 4;
    const int hs = (tid >> 3) & 1;
    const int hl = tid & 7;
    ull war[8];
#pragma unroll
    for (int i = 0; i < 8; ++i)
        war[i] = pk2(Wa[hs * 128 + hl * 16 + i * 2], Wa[hs * 128 + hl * 16 + i * 2 + 1]);
    const float bas = ba[hs];

    float h0o[8], h1o[8];
#pragma unroll
    for (int rr = 0; rr < 8; ++rr) { h0o[rr] = 0.f; h1o[rr] = 0.f; }

    const ulonglong2* w0p = reinterpret_cast<const ulonglong2*>(g_wt[0]) + j;
    const ulonglong2* wip = reinterpret_cast<const ulonglong2*>(g_wt[1]) + j;
    const ulonglong2* whp = reinterpret_cast<const ulonglong2*>(g_wt[2]) + j;

    __syncthreads();

    int p = 0;
    for (int t = -1; t < TT; ++t) {
        // ================= layer 0: gh0 = h0_old @ Wh0^T =================
        ull A0[8], A1[8], A2[8];
#pragma unroll
        for (int rr = 0; rr < 8; ++rr) { A0[rr] = b0p[0]; A1[rr] = b0p[1]; A2[rr] = b0p[2]; }

        {
            const float (*hb)[128] = h0s[p];
#pragma unroll 2
            for (int kq = 0; kq < 32; ++kq) {
                ulonglong2 wA = w0p[kq * 384];
                ulonglong2 wB = w0p[kq * 384 + 128];
                ulonglong2 wC = w0p[kq * 384 + 256];
#pragma unroll
                for (int rr = 0; rr < 8; ++rr) {
                    ulonglong2 h = *reinterpret_cast<const ulonglong2*>(&hb[r0 + rr][kq * 4]);
                    ffma2(A0[rr], wA.x, h.x); ffma2(A0[rr], wA.y, h.y);
                    ffma2(A1[rr], wB.x, h.x); ffma2(A1[rr], wB.y, h.y);
                    ffma2(A2[rr], wC.x, h.x); ffma2(A2[rr], wC.y, h.y);
                }
            }
        }

        // layer-0 epilogue (all operands in regs / tiny LDS)
        {
            float4 d0a = *reinterpret_cast<const float4*>(&decs[0][r0]);
            float4 d0b = *reinterpret_cast<const float4*>(&decs[0][r0 + 4]);
            float4 d1a = *reinterpret_cast<const float4*>(&decs[1][r0]);
            float4 d1b = *reinterpret_cast<const float4*>(&decs[1][r0 + 4]);
            float h0n[8];
#pragma unroll
            for (int rr = 0; rr < 8; ++rr) {
                float d0 = pick8(d0a, d0b, rr), d1 = pick8(d1a, d1b, rr);
                float rg = sigap(cg[0][rr] + d0 * wd0[0] + d1 * wd1[0] + hadd2(A0[rr]));
                float zg = sigap(cg[1][rr] + d0 * wd0[1] + d1 * wd1[1] + hadd2(A1[rr]));
                float ng = tanhap(cg[2][rr] + d0 * wd0[2] + d1 * wd1[2] + rg * hadd2(A2[rr]));
                float hn = ng + zg * (h0o[rr] - ng);
                h0n[rr] = hn;
                h0o[rr] = hn;
            }
#pragma unroll
            for (int rr = 0; rr < 8; ++rr) h0s[p ^ 1][r0 + rr][j] = h0n[rr];
        }
        __syncthreads();   // new h0 visible for layer-1 GEMM

        // ====== layer 1: r/z accumulate both GEMMs fused; n keeps gi/gh split ======
        ull Rz0[8], Rz1[8], Ai[8], Ah[8];
#pragma unroll
        for (int rr = 0; rr < 8; ++rr) {
            Rz0[rr] = brzp[0]; Rz1[rr] = brzp[1]; Ai[rr] = binp; Ah[rr] = bhnp;
        }
        {
            const float (*ha)[128] = h0s[p ^ 1];   // new h0
            const float (*hb)[128] = h1s[p];       // old h1
#pragma unroll 2
            for (int kq = 0; kq < 32; ++kq) {
                ulonglong2 U0 = wip[kq * 384];
                ulonglong2 U1 = wip[kq * 384 + 128];
                ulonglong2 U2 = wip[kq * 384 + 256];
                ulonglong2 V0 = whp[kq * 384];
                ulonglong2 V1 = whp[kq * 384 + 128];
                ulonglong2 V2 = whp[kq * 384 + 256];
#pragma unroll
                for (int rr = 0; rr < 8; ++rr) {
                    ulonglong2 a = *reinterpret_cast<const ulonglong2*>(&ha[r0 + rr][kq * 4]);
                    ulonglong2 b = *reinterpret_cast<const ulonglong2*>(&hb[r0 + rr][kq * 4]);
                    ffma2(Rz0[rr], U0.x, a.x); ffma2(Rz0[rr], U0.y, a.y);
                    ffma2(Rz0[rr], V0.x, b.x); ffma2(Rz0[rr], V0.y, b.y);
                    ffma2(Rz1[rr], U1.x, a.x); ffma2(Rz1[rr], U1.y, a.y);
                    ffma2(Rz1[rr], V1.x, b.x); ffma2(Rz1[rr], V1.y, b.y);
                    ffma2(Ai[rr],  U2.x, a.x); ffma2(Ai[rr],  U2.y, a.y);
                    ffma2(Ah[rr],  V2.x, b.x); ffma2(Ah[rr],  V2.y, b.y);
                }
            }
        }

        // layer-1 epilogue
        {
            float h1n[8];
#pragma unroll
            for (int rr = 0; rr < 8; ++rr) {
                float rg = sigap(hadd2(Rz0[rr]));
                float zg = sigap(hadd2(Rz1[rr]));
                float ng = tanhap(hadd2(Ai[rr]) + rg * hadd2(Ah[rr]));
                float hn = ng + zg * (h1o[rr] - ng);
                h1n[rr] = hn;
                h1o[rr] = hn;
            }
#pragma unroll
            for (int rr = 0; rr < 8; ++rr) h1s[p ^ 1][r0 + rr][j] = h1n[rr];
        }
        __syncthreads();   // new h1 visible for head

        // ========== output head (all 256 threads) + feedback ==========
        if (t >= 0) {
            ull acc = 0ull;
            const float* hrow = &h1s[p ^ 1][hr][hl * 16];
#pragma unroll
            for (int q = 0; q < 4; ++q) {
                ulonglong2 hv = *reinterpret_cast<const ulonglong2*>(&hrow[q * 4]);
                ffma2(acc, war[q * 2], hv.x);
                ffma2(acc, war[q * 2 + 1], hv.y);
            }
            float v = hadd2(acc);
            v += __shfl_xor_sync(0xffffffffu, v, 1, 8);
            v += __shfl_xor_sync(0xffffffffu, v, 2, 8);
            v += __shfl_xor_sync(0xffffffffu, v, 4, 8);
            if (hl == 0) {
                float o = v + bas;
                decs[hs][hr] = o;
                out[(size_t)(brow0 + hr) * (TT * 2) + t * 2 + hs] = o;
            }
        } else {
            if (hl == 0) decs[hs][hr] = x[(size_t)(brow0 + hr) * (TT * 2) + hs];
        }
        __syncthreads();   // decs visible for next step's layer-0 epilogue
        p ^= 1;
    }
}

extern "C" void kernel_launch(void* const* d_in, const int* in_sizes, int n_in,
                              void* d_out, int out_size) {
    const float* x       = (const float*)d_in[0];
    const float* noise_z = (const float*)d_in[1];
    const float* context = (const float*)d_in[2];
    const float* Wi0     = (const float*)d_in[3];
    const float* Wh0     = (const float*)d_in[4];
    const float* bi0     = (const float*)d_in[5];
    const float* bh0     = (const float*)d_in[6];
    const float* Wi1     = (const float*)d_in[7];
    const float* Wh1     = (const float*)d_in[8];
    const float* bi1     = (const float*)d_in[9];
    const float* bh1     = (const float*)d_in[10];
    const float* ba      = (const float*)d_in[12];
    const float* Wa      = (const float*)d_in[11];
    float* out = (float*)d_out;

    transpose_k<<<192, 256>>>(Wh0, Wi1, Wh1);
    gru_kernel<<<NCTA, NTHR>>>(x, noise_z, context, Wi0, bi0, bh0, bi1, bh1, Wa, ba, out);
}